// round 11
// baseline (speedup 1.0000x reference)
#include <cuda_runtime.h>
#include <cstdint>

// Problem constants
#define BATCH 64
#define HDIM 56
#define WDIM 56
#define CDIM 256
#define ROUTES 4
#define CONV_OUT 64
#define ROUTE_W 64            // C / ROUTES
#define ROWG 14               // groups per image: 4 rows each
#define NSTAT 9
#define BN_EPS 1e-3f

// Scratch (device globals — no allocation allowed)
__device__ float g_part[BATCH * ROWG * NSTAT * CDIM];   // 8.3 MB, fully overwritten each call
__device__ float g_W[9 * CDIM * ROUTES];                // folded conv@fc weights / 784
__device__ int   g_route[BATCH];

// ---------------------------------------------------------------------------
// Kernel 1: sufficient statistics (+ fused weight-fold slice).
// grid (14, 65): y<64 -> stats for (batch=y, rowgroup=x); y==64, x<9 -> weff.
//
// Stats blocks: 256 threads = 4 row-slices (s = tid>>6) x 64 channel-quads
// (c4 = tid&63). Slice s covers the whole row h = g*4 + s (fixed parity).
// 56 float4 loads per thread as 7 batches of 8, SOFTWARE-PIPELINED with a
// register double buffer: batch i+1 is issued before batch i is consumed,
// so loads stay outstanding during the FADD phase (duty ~ 1).
// Cross-slice parity combination happens in the 12KB smem reduction.
// stats j: 0=EE 1=EO 2=OE 3=OO 4=R0E 5=R0O 6=C0E 7=C0O 8=P00
// ---------------------------------------------------------------------------
#define LD8(buf, base, bi)                                                \
    do {                                                                  \
        _Pragma("unroll")                                                 \
        for (int _j = 0; _j < 8; ++_j)                                    \
            (buf)[_j] = (base)[(size_t)(8 * (bi) + _j) * (CDIM/4)];       \
    } while (0)

#define CONSUME8(buf)                                                     \
    do {                                                                  \
        _Pragma("unroll")                                                 \
        for (int _j = 0; _j < 8; _j += 2) {                               \
            sE.x += (buf)[_j].x;   sE.y += (buf)[_j].y;                   \
            sE.z += (buf)[_j].z;   sE.w += (buf)[_j].w;                   \
            sO.x += (buf)[_j+1].x; sO.y += (buf)[_j+1].y;                 \
            sO.z += (buf)[_j+1].z; sO.w += (buf)[_j+1].w;                 \
        }                                                                 \
    } while (0)

__global__ __launch_bounds__(256, 3) void k_stats(const float* __restrict__ in,
                                                  const float* __restrict__ conv_w,
                                                  const float* __restrict__ fc_w)
{
    const int tid = threadIdx.x;

    if (blockIdx.y == BATCH) {
        // ---- fused k_weff: fold conv_w [3,3,256,64] with fc_w [64,4] ----
        if (blockIdx.x >= 9) return;
        __shared__ float sf[CONV_OUT * ROUTES];
        const int k  = blockIdx.x;
        sf[tid] = fc_w[tid];
        __syncthreads();
        const float* cw = conv_w + ((size_t)k * CDIM + tid) * CONV_OUT;
        float a0 = 0.f, a1 = 0.f, a2 = 0.f, a3 = 0.f;
        #pragma unroll 16
        for (int co = 0; co < CONV_OUT; ++co) {
            float wv = cw[co];
            a0 += wv * sf[co * 4 + 0];
            a1 += wv * sf[co * 4 + 1];
            a2 += wv * sf[co * 4 + 2];
            a3 += wv * sf[co * 4 + 3];
        }
        const float inv = 1.0f / 784.0f;
        float* o = g_W + ((size_t)k * CDIM + tid) * ROUTES;
        o[0] = a0 * inv; o[1] = a1 * inv; o[2] = a2 * inv; o[3] = a3 * inv;
        return;
    }

    const int b  = blockIdx.y;
    const int g  = blockIdx.x;            // 0..13
    const int c4 = tid & 63;
    const int s  = tid >> 6;              // row within group, 0..3

    const int h = g * 4 + s;
    const float4* row = (const float4*)(in
        + (((size_t)b * HDIM + h) * WDIM) * CDIM) + c4;

    float4 Z = {0.f, 0.f, 0.f, 0.f};
    float4 sE = Z, sO = Z, c0 = Z;

    float4 va[8], vb[8];
    // Pipeline: load batch bi+... ahead of consuming batch bi.
    LD8(va, row, 0);                 // batch 0
    LD8(vb, row, 1);                 // batch 1 in flight
    c0 = va[0];
    CONSUME8(va);                    // consume 0 (batch 2 not yet needed)
    LD8(va, row, 2);  CONSUME8(vb);  // load 2, consume 1
    LD8(vb, row, 3);  CONSUME8(va);  // load 3, consume 2
    LD8(va, row, 4);  CONSUME8(vb);  // load 4, consume 3
    LD8(vb, row, 5);  CONSUME8(va);  // load 5, consume 4
    LD8(va, row, 6);  CONSUME8(vb);  // load 6, consume 5
    CONSUME8(va);                    // consume 6

    // Reduce the 4 row-slices, combining by row parity. 12 KB smem.
    __shared__ float4 sm[4][3][64];
    sm[s][0][c4] = sE;
    sm[s][1][c4] = sO;
    sm[s][2][c4] = c0;
    __syncthreads();

    if (tid < 64) {
        float4 e0 = sm[0][0][tid], o0 = sm[0][1][tid], z0 = sm[0][2][tid]; // row g*4+0 (even)
        float4 e1 = sm[1][0][tid], o1 = sm[1][1][tid], z1 = sm[1][2][tid]; // row g*4+1 (odd)
        float4 e2 = sm[2][0][tid], o2 = sm[2][1][tid], z2 = sm[2][2][tid]; // row g*4+2 (even)
        float4 e3 = sm[3][0][tid], o3 = sm[3][1][tid], z3 = sm[3][2][tid]; // row g*4+3 (odd)

        float4 st[NSTAT];
        st[0].x = e0.x + e2.x; st[0].y = e0.y + e2.y; st[0].z = e0.z + e2.z; st[0].w = e0.w + e2.w;
        st[1].x = o0.x + o2.x; st[1].y = o0.y + o2.y; st[1].z = o0.z + o2.z; st[1].w = o0.w + o2.w;
        st[2].x = e1.x + e3.x; st[2].y = e1.y + e3.y; st[2].z = e1.z + e3.z; st[2].w = e1.w + e3.w;
        st[3].x = o1.x + o3.x; st[3].y = o1.y + o3.y; st[3].z = o1.z + o3.z; st[3].w = o1.w + o3.w;
        st[6].x = z0.x + z2.x; st[6].y = z0.y + z2.y; st[6].z = z0.z + z2.z; st[6].w = z0.w + z2.w;
        st[7].x = z1.x + z3.x; st[7].y = z1.y + z3.y; st[7].z = z1.z + z3.z; st[7].w = z1.w + z3.w;
        float4 Z4 = {0.f, 0.f, 0.f, 0.f};
        st[4] = (g == 0) ? e0 : Z4;   // R0E
        st[5] = (g == 0) ? o0 : Z4;   // R0O
        st[8] = (g == 0) ? z0 : Z4;   // P00

        float4* p = (float4*)(g_part + (((size_t)b * ROWG + g) * NSTAT) * CDIM) + tid;
        #pragma unroll
        for (int j = 0; j < NSTAT; ++j)
            p[(size_t)j * (CDIM/4)] = st[j];
    }
}

// ---------------------------------------------------------------------------
// Kernel 2: per-batch routing logits + argmax.
// grid 64 blocks x 512 threads: thread = (half = tid>>8, ci = tid&255).
// Half h sums groups [h*7, h*7+7). Bias terms added only by half 0.
// ---------------------------------------------------------------------------
__global__ __launch_bounds__(512) void k_route(const float* __restrict__ gamma,
                                               const float* __restrict__ beta,
                                               const float* __restrict__ mmean,
                                               const float* __restrict__ mvar,
                                               const float* __restrict__ conv_b,
                                               const float* __restrict__ fc_w,
                                               const float* __restrict__ fc_b,
                                               float* __restrict__ out_routing)
{
    const int b    = blockIdx.x;
    const int tid  = threadIdx.x;
    const int ci   = tid & 255;
    const int half = tid >> 8;            // 0 or 1

    // Folded weights for this channel: W[k][r], k = kh*3+kw
    float W[9][ROUTES];
    #pragma unroll
    for (int k = 0; k < 9; ++k) {
        const float* w = g_W + ((size_t)k * CDIM + ci) * ROUTES;
        #pragma unroll
        for (int r = 0; r < ROUTES; ++r) W[k][r] = w[r];
    }

    const float scale = rsqrtf(mvar[ci] + BN_EPS) * gamma[ci];

    // Sum partial stats over this half's 7 groups (63 independent loads)
    float st[NSTAT];
    #pragma unroll
    for (int j = 0; j < NSTAT; ++j) st[j] = 0.f;
    const float* p = g_part + ((size_t)b * ROWG + half * 7) * NSTAT * CDIM + ci;
    #pragma unroll
    for (int g = 0; g < 7; ++g) {
        #pragma unroll
        for (int j = 0; j < NSTAT; ++j)
            st[j] += p[((size_t)g * NSTAT + j) * CDIM];
    }

    float acc[ROUTES];
    #pragma unroll
    for (int r = 0; r < ROUTES; ++r) {
        // Inclusion-exclusion coefficients (k = kh*3 + kw)
        float tEE  = W[0][r] + W[2][r] + W[6][r] + W[8][r];
        float tEO  = W[1][r] + W[7][r];
        float tOE  = W[3][r] + W[5][r];
        float tOO  = W[4][r];
        float tR0E = -(W[6][r] + W[8][r]);
        float tR0O = -W[7][r];
        float tC0E = -(W[2][r] + W[8][r]);
        float tC0O = -W[5][r];
        float tP   = W[8][r];

        float dotv = st[0]*tEE + st[1]*tEO + st[2]*tOE + st[3]*tOO
                   + st[4]*tR0E + st[5]*tR0O + st[6]*tC0E + st[7]*tC0O
                   + st[8]*tP;

        acc[r] = scale * dotv;
    }

    // Batch-independent bias terms: only half 0 contributes (once per channel).
    if (half == 0) {
        const float offs = beta[ci] - mmean[ci] * scale;
        #pragma unroll
        for (int r = 0; r < ROUTES; ++r) {
            // valid-count-weighted sum for the BN offset term
            float nsum = 784.f * (W[0][r] + W[1][r] + W[3][r] + W[4][r])
                       + 756.f * (W[2][r] + W[5][r] + W[6][r] + W[7][r])
                       + 729.f *  W[8][r];
            acc[r] += offs * nsum;
        }
        if (ci < CONV_OUT) {
            float cb = conv_b[ci];
            #pragma unroll
            for (int r = 0; r < ROUTES; ++r) acc[r] += cb * fc_w[ci * ROUTES + r];
        }
        if (ci == 0) {
            #pragma unroll
            for (int r = 0; r < ROUTES; ++r) acc[r] += fc_b[r];
        }
    }

    // Block reduction over 512 threads
    #pragma unroll
    for (int r = 0; r < ROUTES; ++r) {
        #pragma unroll
        for (int o = 16; o > 0; o >>= 1)
            acc[r] += __shfl_xor_sync(0xFFFFFFFFu, acc[r], o);
    }
    __shared__ float red[16][ROUTES];
    const int wid = tid >> 5, lane = tid & 31;
    if (lane == 0) {
        #pragma unroll
        for (int r = 0; r < ROUTES; ++r) red[wid][r] = acc[r];
    }
    __syncthreads();
    if (tid == 0) {
        float v[ROUTES];
        #pragma unroll
        for (int r = 0; r < ROUTES; ++r) {
            float s = 0.f;
            #pragma unroll
            for (int w = 0; w < 16; ++w) s += red[w][r];
            v[r] = s;
        }
        int best = 0;
        float bv = v[0];
        #pragma unroll
        for (int r = 1; r < ROUTES; ++r)
            if (v[r] > bv) { bv = v[r]; best = r; }
        g_route[b] = best;
        #pragma unroll
        for (int r = 0; r < ROUTES; ++r) out_routing[b * ROUTES + r] = v[r];
    }
}

// ---------------------------------------------------------------------------
// Kernel 3: gather selected 64-channel slab. 4 float4 per thread (stride 256
// within block, 512B/warp/instruction coalesced) for high MLP. Reverse
// scheduled so the input tail (L2-resident after k_stats) is gathered first.
// grid (13, 64), 256 threads. Per batch: 12544 float4.
// ---------------------------------------------------------------------------
#define G_F4_PER_B (HDIM * WDIM * ROUTE_W / 4)   // 12544
__global__ __launch_bounds__(256) void k_gather(const float* __restrict__ in,
                                                float* __restrict__ out)
{
    const int b = (BATCH - 1) - blockIdx.y;
    const int route = g_route[b];
    const int bx = (gridDim.x - 1) - blockIdx.x;
    const int base = bx * 1024 + threadIdx.x;

    const float4* src4 = (const float4*)in + (size_t)b * (HDIM * WDIM) * (CDIM / 4)
                       + route * (ROUTE_W / 4);
    float4* dst4 = (float4*)out + (size_t)b * G_F4_PER_B;

    #pragma unroll
    for (int m = 0; m < 4; ++m) {
        const int t = base + m * 256;
        if (t < G_F4_PER_B) {
            const int pixel = t >> 4;
            const int q = t & 15;
            dst4[t] = src4[(size_t)pixel * (CDIM / 4) + q];
        }
    }
}

// ---------------------------------------------------------------------------
extern "C" void kernel_launch(void* const* d_in, const int* in_sizes, int n_in,
                              void* d_out, int out_size)
{
    const float* inputs  = (const float*)d_in[0];
    const float* gamma   = (const float*)d_in[1];
    const float* beta    = (const float*)d_in[2];
    const float* mmean   = (const float*)d_in[3];
    const float* mvar    = (const float*)d_in[4];
    const float* conv_w  = (const float*)d_in[5];
    const float* conv_b  = (const float*)d_in[6];
    const float* fc_w    = (const float*)d_in[7];
    const float* fc_b    = (const float*)d_in[8];

    float* out = (float*)d_out;
    // output layout: x [64,56,56,64] then routing_x [64,4]
    float* out_routing = out + ((size_t)out_size - BATCH * ROUTES);

    k_stats<<<dim3(ROWG, BATCH + 1), 256>>>(inputs, conv_w, fc_w);
    k_route<<<BATCH, 512>>>(gamma, beta, mmean, mvar, conv_b, fc_w, fc_b, out_routing);
    k_gather<<<dim3((G_F4_PER_B + 1023) / 1024, BATCH), 256>>>(inputs, out);
}

// round 14
// speedup vs baseline: 1.0500x; 1.0500x over previous
#include <cuda_runtime.h>
#include <cstdint>

// Problem constants
#define BATCH 64
#define HDIM 56
#define WDIM 56
#define CDIM 256
#define ROUTES 4
#define CONV_OUT 64
#define ROUTE_W 64            // C / ROUTES
#define ROWG 14               // groups per image: 4 rows each
#define NSTAT 9
#define BN_EPS 1e-3f

// Scratch (device globals — no allocation allowed)
__device__ float g_part[BATCH * ROWG * NSTAT * CDIM];   // 8.3 MB, fully overwritten each call
__device__ float g_W[9 * CDIM * ROUTES];                // folded conv@fc weights / 784
__device__ int   g_route[BATCH];

// ---------------------------------------------------------------------------
// Kernel 1: sufficient statistics (+ fused weight-fold slice).  [R6 config:
// MLP-8 batches, 4 blocks/SM — measured 36.9us]
// grid (14, 65): y<64 -> stats for (batch=y, rowgroup=x); y==64, x<9 -> weff.
//
// Stats blocks: 256 threads = 4 row-slices (s = tid>>6) x 64 channel-quads
// (c4 = tid&63). Slice s covers the whole row h = g*4 + s (fixed parity),
// channels 4*c4..+3: 56 float4 loads per thread in batches of 8 (MLP=8).
// Cross-slice parity combination happens in the 12KB smem reduction.
// stats j: 0=EE 1=EO 2=OE 3=OO 4=R0E 5=R0O 6=C0E 7=C0O 8=P00
// ---------------------------------------------------------------------------
__global__ __launch_bounds__(256, 4) void k_stats(const float* __restrict__ in,
                                                  const float* __restrict__ conv_w,
                                                  const float* __restrict__ fc_w)
{
    const int tid = threadIdx.x;

    if (blockIdx.y == BATCH) {
        // ---- fused k_weff: fold conv_w [3,3,256,64] with fc_w [64,4] ----
        if (blockIdx.x >= 9) return;
        __shared__ float sf[CONV_OUT * ROUTES];
        const int k  = blockIdx.x;
        sf[tid] = fc_w[tid];
        __syncthreads();
        const float* cw = conv_w + ((size_t)k * CDIM + tid) * CONV_OUT;
        float a0 = 0.f, a1 = 0.f, a2 = 0.f, a3 = 0.f;
        #pragma unroll 16
        for (int co = 0; co < CONV_OUT; ++co) {
            float wv = cw[co];
            a0 += wv * sf[co * 4 + 0];
            a1 += wv * sf[co * 4 + 1];
            a2 += wv * sf[co * 4 + 2];
            a3 += wv * sf[co * 4 + 3];
        }
        const float inv = 1.0f / 784.0f;
        float* o = g_W + ((size_t)k * CDIM + tid) * ROUTES;
        o[0] = a0 * inv; o[1] = a1 * inv; o[2] = a2 * inv; o[3] = a3 * inv;
        return;
    }

    const int b  = blockIdx.y;
    const int g  = blockIdx.x;            // 0..13
    const int c4 = tid & 63;
    const int s  = tid >> 6;              // row within group, 0..3

    const int h = g * 4 + s;
    const float4* row = (const float4*)(in
        + (((size_t)b * HDIM + h) * WDIM) * CDIM) + c4;

    float4 Z = {0.f, 0.f, 0.f, 0.f};
    float4 sE = Z, sO = Z, c0 = Z;

    #pragma unroll
    for (int i = 0; i < 7; ++i) {
        // 8 independent loads issued before any accumulation (MLP = 8)
        float4 v0 = row[(size_t)(8 * i + 0) * (CDIM/4)];
        float4 v1 = row[(size_t)(8 * i + 1) * (CDIM/4)];
        float4 v2 = row[(size_t)(8 * i + 2) * (CDIM/4)];
        float4 v3 = row[(size_t)(8 * i + 3) * (CDIM/4)];
        float4 v4 = row[(size_t)(8 * i + 4) * (CDIM/4)];
        float4 v5 = row[(size_t)(8 * i + 5) * (CDIM/4)];
        float4 v6 = row[(size_t)(8 * i + 6) * (CDIM/4)];
        float4 v7 = row[(size_t)(8 * i + 7) * (CDIM/4)];
        if (i == 0) c0 = v0;
        sE.x += (v0.x + v2.x) + (v4.x + v6.x);
        sE.y += (v0.y + v2.y) + (v4.y + v6.y);
        sE.z += (v0.z + v2.z) + (v4.z + v6.z);
        sE.w += (v0.w + v2.w) + (v4.w + v6.w);
        sO.x += (v1.x + v3.x) + (v5.x + v7.x);
        sO.y += (v1.y + v3.y) + (v5.y + v7.y);
        sO.z += (v1.z + v3.z) + (v5.z + v7.z);
        sO.w += (v1.w + v3.w) + (v5.w + v7.w);
    }

    // Reduce the 4 row-slices, combining by row parity. 12 KB smem.
    __shared__ float4 sm[4][3][64];
    sm[s][0][c4] = sE;
    sm[s][1][c4] = sO;
    sm[s][2][c4] = c0;
    __syncthreads();

    if (tid < 64) {
        float4 e0 = sm[0][0][tid], o0 = sm[0][1][tid], z0 = sm[0][2][tid]; // row g*4+0 (even)
        float4 e1 = sm[1][0][tid], o1 = sm[1][1][tid], z1 = sm[1][2][tid]; // row g*4+1 (odd)
        float4 e2 = sm[2][0][tid], o2 = sm[2][1][tid], z2 = sm[2][2][tid]; // row g*4+2 (even)
        float4 e3 = sm[3][0][tid], o3 = sm[3][1][tid], z3 = sm[3][2][tid]; // row g*4+3 (odd)

        float4 st[NSTAT];
        st[0].x = e0.x + e2.x; st[0].y = e0.y + e2.y; st[0].z = e0.z + e2.z; st[0].w = e0.w + e2.w;
        st[1].x = o0.x + o2.x; st[1].y = o0.y + o2.y; st[1].z = o0.z + o2.z; st[1].w = o0.w + o2.w;
        st[2].x = e1.x + e3.x; st[2].y = e1.y + e3.y; st[2].z = e1.z + e3.z; st[2].w = e1.w + e3.w;
        st[3].x = o1.x + o3.x; st[3].y = o1.y + o3.y; st[3].z = o1.z + o3.z; st[3].w = o1.w + o3.w;
        st[6].x = z0.x + z2.x; st[6].y = z0.y + z2.y; st[6].z = z0.z + z2.z; st[6].w = z0.w + z2.w;
        st[7].x = z1.x + z3.x; st[7].y = z1.y + z3.y; st[7].z = z1.z + z3.z; st[7].w = z1.w + z3.w;
        float4 Z4 = {0.f, 0.f, 0.f, 0.f};
        st[4] = (g == 0) ? e0 : Z4;   // R0E
        st[5] = (g == 0) ? o0 : Z4;   // R0O
        st[8] = (g == 0) ? z0 : Z4;   // P00

        float4* p = (float4*)(g_part + (((size_t)b * ROWG + g) * NSTAT) * CDIM) + tid;
        #pragma unroll
        for (int j = 0; j < NSTAT; ++j)
            p[(size_t)j * (CDIM/4)] = st[j];
    }
}

// ---------------------------------------------------------------------------
// Kernel 2: per-batch routing logits + argmax.  [R10 split config]
// grid 64 blocks x 512 threads: thread = (half = tid>>8, ci = tid&255).
// Half h sums groups [h*7, h*7+7). Bias terms added only by half 0.
// ---------------------------------------------------------------------------
__global__ __launch_bounds__(512) void k_route(const float* __restrict__ gamma,
                                               const float* __restrict__ beta,
                                               const float* __restrict__ mmean,
                                               const float* __restrict__ mvar,
                                               const float* __restrict__ conv_b,
                                               const float* __restrict__ fc_w,
                                               const float* __restrict__ fc_b,
                                               float* __restrict__ out_routing)
{
    const int b    = blockIdx.x;
    const int tid  = threadIdx.x;
    const int ci   = tid & 255;
    const int half = tid >> 8;            // 0 or 1

    // Folded weights for this channel: W[k][r], k = kh*3+kw
    float W[9][ROUTES];
    #pragma unroll
    for (int k = 0; k < 9; ++k) {
        const float* w = g_W + ((size_t)k * CDIM + ci) * ROUTES;
        #pragma unroll
        for (int r = 0; r < ROUTES; ++r) W[k][r] = w[r];
    }

    const float scale = rsqrtf(mvar[ci] + BN_EPS) * gamma[ci];

    // Sum partial stats over this half's 7 groups (63 independent loads)
    float st[NSTAT];
    #pragma unroll
    for (int j = 0; j < NSTAT; ++j) st[j] = 0.f;
    const float* p = g_part + ((size_t)b * ROWG + half * 7) * NSTAT * CDIM + ci;
    #pragma unroll
    for (int g = 0; g < 7; ++g) {
        #pragma unroll
        for (int j = 0; j < NSTAT; ++j)
            st[j] += p[((size_t)g * NSTAT + j) * CDIM];
    }

    float acc[ROUTES];
    #pragma unroll
    for (int r = 0; r < ROUTES; ++r) {
        // Inclusion-exclusion coefficients (k = kh*3 + kw)
        float tEE  = W[0][r] + W[2][r] + W[6][r] + W[8][r];
        float tEO  = W[1][r] + W[7][r];
        float tOE  = W[3][r] + W[5][r];
        float tOO  = W[4][r];
        float tR0E = -(W[6][r] + W[8][r]);
        float tR0O = -W[7][r];
        float tC0E = -(W[2][r] + W[8][r]);
        float tC0O = -W[5][r];
        float tP   = W[8][r];

        float dotv = st[0]*tEE + st[1]*tEO + st[2]*tOE + st[3]*tOO
                   + st[4]*tR0E + st[5]*tR0O + st[6]*tC0E + st[7]*tC0O
                   + st[8]*tP;

        acc[r] = scale * dotv;
    }

    // Batch-independent bias terms: only half 0 contributes (once per channel).
    if (half == 0) {
        const float offs = beta[ci] - mmean[ci] * scale;
        #pragma unroll
        for (int r = 0; r < ROUTES; ++r) {
            // valid-count-weighted sum for the BN offset term
            float nsum = 784.f * (W[0][r] + W[1][r] + W[3][r] + W[4][r])
                       + 756.f * (W[2][r] + W[5][r] + W[6][r] + W[7][r])
                       + 729.f *  W[8][r];
            acc[r] += offs * nsum;
        }
        if (ci < CONV_OUT) {
            float cb = conv_b[ci];
            #pragma unroll
            for (int r = 0; r < ROUTES; ++r) acc[r] += cb * fc_w[ci * ROUTES + r];
        }
        if (ci == 0) {
            #pragma unroll
            for (int r = 0; r < ROUTES; ++r) acc[r] += fc_b[r];
        }
    }

    // Block reduction over 512 threads
    #pragma unroll
    for (int r = 0; r < ROUTES; ++r) {
        #pragma unroll
        for (int o = 16; o > 0; o >>= 1)
            acc[r] += __shfl_xor_sync(0xFFFFFFFFu, acc[r], o);
    }
    __shared__ float red[16][ROUTES];
    const int wid = tid >> 5, lane = tid & 31;
    if (lane == 0) {
        #pragma unroll
        for (int r = 0; r < ROUTES; ++r) red[wid][r] = acc[r];
    }
    __syncthreads();
    if (tid == 0) {
        float v[ROUTES];
        #pragma unroll
        for (int r = 0; r < ROUTES; ++r) {
            float s = 0.f;
            #pragma unroll
            for (int w = 0; w < 16; ++w) s += red[w][r];
            v[r] = s;
        }
        int best = 0;
        float bv = v[0];
        #pragma unroll
        for (int r = 1; r < ROUTES; ++r)
            if (v[r] > bv) { bv = v[r]; best = r; }
        g_route[b] = best;
        #pragma unroll
        for (int r = 0; r < ROUTES; ++r) out_routing[b * ROUTES + r] = v[r];
    }
}

// ---------------------------------------------------------------------------
// Kernel 3: gather selected 64-channel slab. 4 float4 per thread (stride 256
// within block, 512B/warp/instruction coalesced) for high MLP. Reverse
// scheduled so the input tail (L2-resident after k_stats) is gathered first.
// grid (13, 64), 256 threads. Per batch: 12544 float4.
// ---------------------------------------------------------------------------
#define G_F4_PER_B (HDIM * WDIM * ROUTE_W / 4)   // 12544
__global__ __launch_bounds__(256) void k_gather(const float* __restrict__ in,
                                                float* __restrict__ out)
{
    const int b = (BATCH - 1) - blockIdx.y;
    const int route = g_route[b];
    const int bx = (gridDim.x - 1) - blockIdx.x;
    const int base = bx * 1024 + threadIdx.x;

    const float4* src4 = (const float4*)in + (size_t)b * (HDIM * WDIM) * (CDIM / 4)
                       + route * (ROUTE_W / 4);
    float4* dst4 = (float4*)out + (size_t)b * G_F4_PER_B;

    #pragma unroll
    for (int m = 0; m < 4; ++m) {
        const int t = base + m * 256;
        if (t < G_F4_PER_B) {
            const int pixel = t >> 4;
            const int q = t & 15;
            dst4[t] = src4[(size_t)pixel * (CDIM / 4) + q];
        }
    }
}

// ---------------------------------------------------------------------------
extern "C" void kernel_launch(void* const* d_in, const int* in_sizes, int n_in,
                              void* d_out, int out_size)
{
    const float* inputs  = (const float*)d_in[0];
    const float* gamma   = (const float*)d_in[1];
    const float* beta    = (const float*)d_in[2];
    const float* mmean   = (const float*)d_in[3];
    const float* mvar    = (const float*)d_in[4];
    const float* conv_w  = (const float*)d_in[5];
    const float* conv_b  = (const float*)d_in[6];
    const float* fc_w    = (const float*)d_in[7];
    const float* fc_b    = (const float*)d_in[8];

    float* out = (float*)d_out;
    // output layout: x [64,56,56,64] then routing_x [64,4]
    float* out_routing = out + ((size_t)out_size - BATCH * ROUTES);

    k_stats<<<dim3(ROWG, BATCH + 1), 256>>>(inputs, conv_w, fc_w);
    k_route<<<BATCH, 512>>>(gamma, beta, mmean, mvar, conv_b, fc_w, fc_b, out_routing);
    k_gather<<<dim3((G_F4_PER_B + 1023) / 1024, BATCH), 256>>>(inputs, out);
}